// round 12
// baseline (speedup 1.0000x reference)
#include <cuda_runtime.h>
#include <cuda_bf16.h>
#include <cstdint>
#include <float.h>

#define BATCH 64
#define NPER  2048
#define DIM   64
#define KNN   16
#define CAND  20
#define NTOT  (BATCH * NPER)

// scratch (no cudaMalloc allowed)
__device__ float d_sq[NTOT];
__device__ float d_P1[NTOT * DIM];     // X @ W1^T
__device__ float d_C[NTOT * DIM];      // X @ W2^T
__device__ int   d_cand[NTOT * CAND];  // approx top-20 candidates (global idx)
__device__ int   d_idx[NTOT * KNN];    // exact top-16 (global idx)

// ===========================================================================
// warp-MMA helpers (base sm_103 target: mma.sync + ldmatrix, NO tcgen05)
// ===========================================================================
__device__ __forceinline__ uint32_t smem_u32(const void* p) {
    uint32_t a;
    asm("{ .reg .u64 t; cvta.to.shared.u64 t, %1; cvt.u32.u64 %0, t; }" : "=r"(a) : "l"(p));
    return a;
}
__device__ __forceinline__ void ldmatrix_x4(uint32_t& r0, uint32_t& r1, uint32_t& r2, uint32_t& r3, uint32_t addr) {
    asm volatile("ldmatrix.sync.aligned.m8n8.x4.shared.b16 {%0,%1,%2,%3},[%4];"
                 : "=r"(r0), "=r"(r1), "=r"(r2), "=r"(r3) : "r"(addr));
}
__device__ __forceinline__ void mma_bf16(float* d, const uint32_t* a, uint32_t b0, uint32_t b1) {
    asm volatile("mma.sync.aligned.m16n8k16.row.col.f32.bf16.bf16.f32 "
                 "{%0,%1,%2,%3}, {%4,%5,%6,%7}, {%8,%9}, {%0,%1,%2,%3};"
                 : "+f"(d[0]), "+f"(d[1]), "+f"(d[2]), "+f"(d[3])
                 : "r"(a[0]), "r"(a[1]), "r"(a[2]), "r"(a[3]), "r"(b0), "r"(b1));
}

// ---------------------------------------------------------------------------
// Kernel 1: GEMM half: X[131072 x 64] @ Wh^T[64 x 64], h = blockIdx.y (W1/W2).
// ---------------------------------------------------------------------------
#define XT_STRIDE 68
__global__ __launch_bounds__(256) void precompute_kernel(
    const float* __restrict__ x, const float* __restrict__ weight)
{
    __shared__ float s_v[DIM * 64];          // [d][o]      16 KB
    __shared__ float s_xt[64 * XT_STRIDE];   // [p][d] pad  17 KB

    int tid   = threadIdx.x;
    int nbase = blockIdx.x * 64;
    int h     = blockIdx.y;

    for (int t = tid; t < DIM * 64; t += 256) {
        int o = t >> 6, d = t & 63;
        s_v[d * 64 + o] = weight[o * 128 + h * 64 + d];
    }
    for (int t = tid; t < 64 * 64; t += 256) {
        int p = t >> 6, d = t & 63;
        s_xt[p * XT_STRIDE + d] = x[(size_t)(nbase + p) * DIM + d];
    }
    __syncthreads();

    if (h == 0) {
        int p = tid >> 2, q = tid & 3;
        float ss = 0.f;
        #pragma unroll
        for (int s = 0; s < 16; ++s) {
            float v = s_xt[p * XT_STRIDE + q * 16 + s];
            ss = fmaf(v, v, ss);
        }
        ss += __shfl_xor_sync(0xffffffffu, ss, 1);
        ss += __shfl_xor_sync(0xffffffffu, ss, 2);
        if (q == 0) d_sq[nbase + p] = ss;
    }

    int og = tid & 15, pg = tid >> 4;
    int j_base = og * 4, p_base = pg * 4;

    float acc[4][4];
    #pragma unroll
    for (int pi = 0; pi < 4; ++pi)
        #pragma unroll
        for (int jj = 0; jj < 4; ++jj) acc[pi][jj] = 0.f;

    #pragma unroll
    for (int d4 = 0; d4 < 16; ++d4) {
        float4 xv[4];
        #pragma unroll
        for (int pi = 0; pi < 4; ++pi)
            xv[pi] = *(const float4*)&s_xt[(p_base + pi) * XT_STRIDE + d4 * 4];
        #pragma unroll
        for (int dd = 0; dd < 4; ++dd) {
            float4 wv = *(const float4*)&s_v[(d4 * 4 + dd) * 64 + j_base];
            float xs[4] = { ((const float*)&xv[0])[dd], ((const float*)&xv[1])[dd],
                            ((const float*)&xv[2])[dd], ((const float*)&xv[3])[dd] };
            #pragma unroll
            for (int pi = 0; pi < 4; ++pi) {
                acc[pi][0] = fmaf(xs[pi], wv.x, acc[pi][0]);
                acc[pi][1] = fmaf(xs[pi], wv.y, acc[pi][1]);
                acc[pi][2] = fmaf(xs[pi], wv.z, acc[pi][2]);
                acc[pi][3] = fmaf(xs[pi], wv.w, acc[pi][3]);
            }
        }
    }

    float* dst = h ? d_C : d_P1;
    #pragma unroll
    for (int pi = 0; pi < 4; ++pi) {
        *(float4*)&dst[(size_t)(nbase + p_base + pi) * DIM + j_base] =
            make_float4(acc[pi][0], acc[pi][1], acc[pi][2], acc[pi][3]);
    }
}

// ---------------------------------------------------------------------------
// Kernel 2: approximate kNN via warp mma.sync (bf16 hi/lo, 3 products).
// CTA = 128 i-points x 256 threads. Warp w owns i-rows [16w,16w+16):
// computes their S rows, then warp-cooperatively maintains their smem
// top-20 lists (ballot + shfl_up insertion; uniform control flow).
// ---------------------------------------------------------------------------
#define OFF_SQ   0
#define OFF_XI_H 512
#define OFF_XI_L (OFF_XI_H + 16384)
#define OFF_XJ_H (OFF_XI_L + 16384)
#define OFF_XJ_L (OFF_XJ_H + 16384)
#define OFF_S    (OFF_XJ_L + 16384)
#define S_STRIDE 65
#define OFF_LK   (OFF_S + 128 * S_STRIDE * 4)
#define OFF_LI   (OFF_LK + 128 * CAND * 4)
#define KNN_SMEM (OFF_LI + 128 * CAND * 2)

__device__ __forceinline__ void stage_tile(const float* __restrict__ x, int gbase,
                                           char* smem, int hi_off, int lo_off, int tid)
{
    const float2* xg = (const float2*)(x) + (size_t)gbase * 32;
    #pragma unroll
    for (int it = 0; it < 16; ++it) {
        int t = it * 256 + tid;          // 4096 b32 slots
        int r = t >> 5, c4 = t & 31;
        float2 v = xg[r * 32 + c4];
        __nv_bfloat16 h0 = __float2bfloat16(v.x);
        __nv_bfloat16 h1 = __float2bfloat16(v.y);
        __nv_bfloat16 l0 = __float2bfloat16(v.x - __bfloat162float(h0));
        __nv_bfloat16 l1 = __float2bfloat16(v.y - __bfloat162float(h1));
        uint32_t hp = (uint32_t)__bfloat16_as_ushort(h0) | ((uint32_t)__bfloat16_as_ushort(h1) << 16);
        uint32_t lp = (uint32_t)__bfloat16_as_ushort(l0) | ((uint32_t)__bfloat16_as_ushort(l1) << 16);
        int q  = (c4 >> 2) ^ (r & 7);                    // permuted 16B chunk
        int by = r * 128 + q * 16 + (c4 & 3) * 4;
        *(uint32_t*)(smem + hi_off + by) = hp;
        *(uint32_t*)(smem + lo_off + by) = lp;
    }
}

__device__ __forceinline__ uint32_t tile_addr(uint32_t base, int r, int c) {
    return base + r * 128 + ((c ^ (r & 7)) << 4);
}

// warp-cooperative sorted insert into smem list of row r (ascending keys)
__device__ __forceinline__ void list_insert(float* listK, uint16_t* listI,
                                            int r, float kn, uint32_t jn, int lane)
{
    float    lk = FLT_MAX;
    uint32_t li = 0;
    if (lane < CAND) {
        lk = listK[r * CAND + lane];
        li = listI[r * CAND + lane];
    }
    uint32_t bal = __ballot_sync(0xffffffffu, (lane < CAND) && (lk > kn));
    int pos = CAND - __popc(bal);
    float    pk = __shfl_up_sync(0xffffffffu, lk, 1);
    uint32_t pi = __shfl_up_sync(0xffffffffu, li, 1);
    if (lane < CAND) {
        if (lane == pos)      { listK[r * CAND + lane] = kn; listI[r * CAND + lane] = (uint16_t)jn; }
        else if (lane > pos)  { listK[r * CAND + lane] = pk; listI[r * CAND + lane] = (uint16_t)pi; }
    }
}

__global__ void __launch_bounds__(256, 2) knn_tc_kernel(const float* __restrict__ x)
{
    extern __shared__ char smem[];
    uint32_t sb = smem_u32(smem);
    float*     sqs   = (float*)(smem + OFF_SQ);
    float*     S     = (float*)(smem + OFF_S);
    float*     listK = (float*)(smem + OFF_LK);
    uint16_t*  listI = (uint16_t*)(smem + OFF_LI);

    int tid  = threadIdx.x;
    int w    = tid >> 5, lane = tid & 31;
    int b    = blockIdx.y;
    int gi0  = b * NPER + blockIdx.x * 128;

    // init candidate lists
    for (int t = tid; t < 128 * CAND; t += 256) { listK[t] = FLT_MAX; listI[t] = 0; }

    stage_tile(x, gi0, smem, OFF_XI_H, OFF_XI_L, tid);
    __syncthreads();

    // persistent A fragments: warp w = i-rows [16w, 16w+16)
    uint32_t ah[4][4], al[4][4];
    {
        int r = w * 16 + (lane & 15);
        int qh = (lane >> 4);
        #pragma unroll
        for (int ks = 0; ks < 4; ++ks) {
            ldmatrix_x4(ah[ks][0], ah[ks][1], ah[ks][2], ah[ks][3],
                        tile_addr(sb + OFF_XI_H, r, 2 * ks + qh));
            ldmatrix_x4(al[ks][0], al[ks][1], al[ks][2], al[ks][3],
                        tile_addr(sb + OFF_XI_L, r, 2 * ks + qh));
        }
    }
    __syncthreads();   // A-frag reads done before any future XI reuse (none) / uniformity

    for (int t = 0; t < NPER / 128; ++t) {
        int jt = t * 128;
        stage_tile(x, b * NPER + jt, smem, OFF_XJ_H, OFF_XJ_L, tid);
        if (tid < 128) sqs[tid] = d_sq[b * NPER + jt + tid];
        __syncthreads();

        #pragma unroll
        for (int h = 0; h < 2; ++h) {
            // ---- MMA: warp computes its 16 rows x 64 cols ----
            float acc[8][4];
            #pragma unroll
            for (int nt = 0; nt < 8; ++nt)
                #pragma unroll
                for (int c = 0; c < 4; ++c) acc[nt][c] = 0.f;

            // B frags via x4: lane groups give (nt, k-lo), (nt, k-hi), (nt+1, k-lo), (nt+1, k-hi)
            int m    = lane >> 3;
            int brow0 = h * 64 + (m >> 1) * 8 + (lane & 7);
            int bchk  = (m & 1);
            #pragma unroll
            for (int ntb = 0; ntb < 8; ntb += 2) {
                int brow = brow0 + ntb * 8;
                #pragma unroll
                for (int ks = 0; ks < 4; ++ks) {
                    uint32_t h0, h1, h2, h3, l0, l1, l2, l3;
                    ldmatrix_x4(h0, h1, h2, h3, tile_addr(sb + OFF_XJ_H, brow, 2 * ks + bchk));
                    ldmatrix_x4(l0, l1, l2, l3, tile_addr(sb + OFF_XJ_L, brow, 2 * ks + bchk));
                    mma_bf16(acc[ntb],     ah[ks], h0, h1);
                    mma_bf16(acc[ntb],     al[ks], h0, h1);
                    mma_bf16(acc[ntb],     ah[ks], l0, l1);
                    mma_bf16(acc[ntb + 1], ah[ks], h2, h3);
                    mma_bf16(acc[ntb + 1], al[ks], h2, h3);
                    mma_bf16(acc[ntb + 1], ah[ks], l2, l3);
                }
            }

            // store S rows (warp-private rows, no cross-warp sync needed)
            int r0 = w * 16 + (lane >> 2);
            int c0 = (lane & 3) * 2;
            #pragma unroll
            for (int nt = 0; nt < 8; ++nt) {
                int c = nt * 8 + c0;
                S[r0 * S_STRIDE + c]           = acc[nt][0];
                S[r0 * S_STRIDE + c + 1]       = acc[nt][1];
                S[(r0 + 8) * S_STRIDE + c]     = acc[nt][2];
                S[(r0 + 8) * S_STRIDE + c + 1] = acc[nt][3];
            }
            __syncwarp();

            // ---- scan: warp-cooperative top-20 over its 16 rows ----
            int jbase = jt + h * 64;
            #pragma unroll 1
            for (int rr = 0; rr < 16; ++rr) {
                int r = w * 16 + rr;
                float worst = listK[r * CAND + CAND - 1];
                float k0 = fmaf(-2.f, S[r * S_STRIDE + lane],      sqs[h * 64 + lane]);
                float k1 = fmaf(-2.f, S[r * S_STRIDE + 32 + lane], sqs[h * 64 + 32 + lane]);
                uint32_t b0 = __ballot_sync(0xffffffffu, k0 < worst);
                uint32_t b1 = __ballot_sync(0xffffffffu, k1 < worst);
                while (b0) {
                    int src = __ffs(b0) - 1; b0 &= b0 - 1;
                    float kn = __shfl_sync(0xffffffffu, k0, src);
                    if (kn < worst) {
                        list_insert(listK, listI, r, kn, (uint32_t)(jbase + src), lane);
                        worst = listK[r * CAND + CAND - 1];
                    }
                }
                while (b1) {
                    int src = __ffs(b1) - 1; b1 &= b1 - 1;
                    float kn = __shfl_sync(0xffffffffu, k1, src);
                    if (kn < worst) {
                        list_insert(listK, listI, r, kn, (uint32_t)(jbase + 32 + src), lane);
                        worst = listK[r * CAND + CAND - 1];
                    }
                }
            }
            __syncwarp();
        }
        __syncthreads();   // all warps done with XJ before restage
    }

    // write candidate sets
    for (int t = tid; t < 128 * CAND; t += 256) {
        int r = t / CAND, k = t % CAND;
        d_cand[(size_t)(gi0 + r) * CAND + k] = b * NPER + (int)listI[r * CAND + k];
    }
}

// ---------------------------------------------------------------------------
// Kernel 2b: exact fp32 rescore of the 20 candidates -> true top-16.
// Warp per point. key = sq_j - 2*dot (fp32), stable tie-break by smaller j.
// ---------------------------------------------------------------------------
__global__ __launch_bounds__(256) void rescore_kernel(const float* __restrict__ x)
{
    int warp = threadIdx.x >> 5, lane = threadIdx.x & 31;
    int n = blockIdx.x * 8 + warp;

    float xi0 = x[(size_t)n * DIM + lane];
    float xi1 = x[(size_t)n * DIM + 32 + lane];

    int cid = (lane < CAND) ? d_cand[n * CAND + lane] : 0;

    float myKey = FLT_MAX;
    int   myJ   = 0x7fffffff;
    #pragma unroll
    for (int c = 0; c < CAND; ++c) {
        int j = __shfl_sync(0xffffffffu, cid, c);
        float p = xi0 * x[(size_t)j * DIM + lane] + xi1 * x[(size_t)j * DIM + 32 + lane];
        #pragma unroll
        for (int off = 16; off; off >>= 1) p += __shfl_xor_sync(0xffffffffu, p, off);
        if (lane == c) { myKey = fmaf(-2.f, p, d_sq[j]); myJ = j; }
    }

    int rank = 0;
    #pragma unroll
    for (int m = 0; m < CAND; ++m) {
        float km = __shfl_sync(0xffffffffu, myKey, m);
        int   jm = __shfl_sync(0xffffffffu, myJ,   m);
        rank += (km < myKey) || (km == myKey && jm < myJ);
    }
    if (lane < CAND && rank < KNN) d_idx[n * KNN + rank] = myJ;
}

// ---------------------------------------------------------------------------
// Kernel 3: out[n][o] = relu(P1[n][o] - C[n][o] + bias[o] + max_k C[idx[n][k]][o])
// ---------------------------------------------------------------------------
__global__ __launch_bounds__(256) void gather_kernel(
    float* __restrict__ out, const float* __restrict__ bias)
{
    int warp = threadIdx.x >> 5, lane = threadIdx.x & 31;
    int n = blockIdx.x * 8 + warp;

    int myidx = 0;
    if (lane < KNN) myidx = d_idx[n * KNN + lane];

    float m0 = -FLT_MAX, m1 = -FLT_MAX;
    #pragma unroll
    for (int k = 0; k < KNN; ++k) {
        int j = __shfl_sync(0xffffffffu, myidx, k);
        m0 = fmaxf(m0, d_C[j * DIM + lane]);
        m1 = fmaxf(m1, d_C[j * DIM + 32 + lane]);
    }
    float a0 = d_P1[n * DIM + lane]      - d_C[n * DIM + lane]      + bias[lane];
    float a1 = d_P1[n * DIM + 32 + lane] - d_C[n * DIM + 32 + lane] + bias[32 + lane];
    out[n * DIM + lane]      = fmaxf(a0 + m0, 0.f);
    out[n * DIM + 32 + lane] = fmaxf(a1 + m1, 0.f);
}

// ---------------------------------------------------------------------------
extern "C" void kernel_launch(void* const* d_in, const int* in_sizes, int n_in,
                              void* d_out, int out_size)
{
    const float* x      = (const float*)d_in[0];
    // d_in[1] = batch (structure known: repeat(arange(64), 2048)) — unused
    const float* weight = (const float*)d_in[2];
    const float* bias   = (const float*)d_in[3];
    float* out = (float*)d_out;

    cudaFuncSetAttribute(knn_tc_kernel, cudaFuncAttributeMaxDynamicSharedMemorySize, KNN_SMEM);

    precompute_kernel<<<dim3(NTOT / 64, 2), 256>>>(x, weight);
    knn_tc_kernel<<<dim3(NPER / 128, BATCH), 256, KNN_SMEM>>>(x);
    rescore_kernel<<<NTOT / 8, 256>>>(x);
    gather_kernel<<<NTOT / 8, 256>>>(out, bias);
}

// round 13
// speedup vs baseline: 1.1345x; 1.1345x over previous
#include <cuda_runtime.h>
#include <cuda_bf16.h>
#include <cstdint>
#include <float.h>

#define BATCH 64
#define NPER  2048
#define DIM   64
#define KNN   16
#define HCAND 16              // per-thread (per j-half) candidates
#define CAND  32              // union per row
#define NTOT  (BATCH * NPER)

// scratch (no cudaMalloc allowed)
__device__ float d_sq[NTOT];
__device__ float d_P1[NTOT * DIM];     // X @ W1^T
__device__ float d_C[NTOT * DIM];      // X @ W2^T
__device__ int   d_cand[NTOT * CAND];  // approx candidates (global idx)

// ===========================================================================
// warp-MMA helpers (base sm_103 target: mma.sync + ldmatrix, NO tcgen05)
// ===========================================================================
__device__ __forceinline__ uint32_t smem_u32(const void* p) {
    uint32_t a;
    asm("{ .reg .u64 t; cvta.to.shared.u64 t, %1; cvt.u32.u64 %0, t; }" : "=r"(a) : "l"(p));
    return a;
}
__device__ __forceinline__ void ldmatrix_x4(uint32_t& r0, uint32_t& r1, uint32_t& r2, uint32_t& r3, uint32_t addr) {
    asm volatile("ldmatrix.sync.aligned.m8n8.x4.shared.b16 {%0,%1,%2,%3},[%4];"
                 : "=r"(r0), "=r"(r1), "=r"(r2), "=r"(r3) : "r"(addr));
}
__device__ __forceinline__ void ldmatrix_x2(uint32_t& r0, uint32_t& r1, uint32_t addr) {
    asm volatile("ldmatrix.sync.aligned.m8n8.x2.shared.b16 {%0,%1},[%2];"
                 : "=r"(r0), "=r"(r1) : "r"(addr));
}
__device__ __forceinline__ void mma_bf16(float* d, const uint32_t* a, uint32_t b0, uint32_t b1) {
    asm volatile("mma.sync.aligned.m16n8k16.row.col.f32.bf16.bf16.f32 "
                 "{%0,%1,%2,%3}, {%4,%5,%6,%7}, {%8,%9}, {%0,%1,%2,%3};"
                 : "+f"(d[0]), "+f"(d[1]), "+f"(d[2]), "+f"(d[3])
                 : "r"(a[0]), "r"(a[1]), "r"(a[2]), "r"(a[3]), "r"(b0), "r"(b1));
}

// ---------------------------------------------------------------------------
// Kernel 1: GEMM half: X[131072 x 64] @ Wh^T[64 x 64], h = blockIdx.y (W1/W2).
// ---------------------------------------------------------------------------
#define XT_STRIDE 68
__global__ __launch_bounds__(256) void precompute_kernel(
    const float* __restrict__ x, const float* __restrict__ weight)
{
    __shared__ float s_v[DIM * 64];          // [d][o]      16 KB
    __shared__ float s_xt[64 * XT_STRIDE];   // [p][d] pad  17 KB

    int tid   = threadIdx.x;
    int nbase = blockIdx.x * 64;
    int h     = blockIdx.y;

    for (int t = tid; t < DIM * 64; t += 256) {
        int o = t >> 6, d = t & 63;
        s_v[d * 64 + o] = weight[o * 128 + h * 64 + d];
    }
    for (int t = tid; t < 64 * 64; t += 256) {
        int p = t >> 6, d = t & 63;
        s_xt[p * XT_STRIDE + d] = x[(size_t)(nbase + p) * DIM + d];
    }
    __syncthreads();

    if (h == 0) {
        int p = tid >> 2, q = tid & 3;
        float ss = 0.f;
        #pragma unroll
        for (int s = 0; s < 16; ++s) {
            float v = s_xt[p * XT_STRIDE + q * 16 + s];
            ss = fmaf(v, v, ss);
        }
        ss += __shfl_xor_sync(0xffffffffu, ss, 1);
        ss += __shfl_xor_sync(0xffffffffu, ss, 2);
        if (q == 0) d_sq[nbase + p] = ss;
    }

    int og = tid & 15, pg = tid >> 4;
    int j_base = og * 4, p_base = pg * 4;

    float acc[4][4];
    #pragma unroll
    for (int pi = 0; pi < 4; ++pi)
        #pragma unroll
        for (int jj = 0; jj < 4; ++jj) acc[pi][jj] = 0.f;

    #pragma unroll
    for (int d4 = 0; d4 < 16; ++d4) {
        float4 xv[4];
        #pragma unroll
        for (int pi = 0; pi < 4; ++pi)
            xv[pi] = *(const float4*)&s_xt[(p_base + pi) * XT_STRIDE + d4 * 4];
        #pragma unroll
        for (int dd = 0; dd < 4; ++dd) {
            float4 wv = *(const float4*)&s_v[(d4 * 4 + dd) * 64 + j_base];
            float xs[4] = { ((const float*)&xv[0])[dd], ((const float*)&xv[1])[dd],
                            ((const float*)&xv[2])[dd], ((const float*)&xv[3])[dd] };
            #pragma unroll
            for (int pi = 0; pi < 4; ++pi) {
                acc[pi][0] = fmaf(xs[pi], wv.x, acc[pi][0]);
                acc[pi][1] = fmaf(xs[pi], wv.y, acc[pi][1]);
                acc[pi][2] = fmaf(xs[pi], wv.z, acc[pi][2]);
                acc[pi][3] = fmaf(xs[pi], wv.w, acc[pi][3]);
            }
        }
    }

    float* dst = h ? d_C : d_P1;
    #pragma unroll
    for (int pi = 0; pi < 4; ++pi) {
        *(float4*)&dst[(size_t)(nbase + p_base + pi) * DIM + j_base] =
            make_float4(acc[pi][0], acc[pi][1], acc[pi][2], acc[pi][3]);
    }
}

// ---------------------------------------------------------------------------
// Kernel 2: approximate kNN via warp mma.sync (bf16 hi/lo, 3 products).
// CTA = 128 i-points x 256 threads. Scan split by j-halves:
// thread t<128 scans row t, cols 0-31; thread t+128 scans row t, cols 32-63.
// Each keeps a register top-16 (guarded insertion). Union = 32 candidates.
// ---------------------------------------------------------------------------
#define OFF_SQ   0
#define OFF_XI_H 1024
#define OFF_XI_L (OFF_XI_H + 16384)
#define OFF_XJ_H (OFF_XI_L + 16384)
#define OFF_XJ_L (OFF_XJ_H + 16384)
#define OFF_S    (OFF_XJ_L + 16384)
#define S_STRIDE 65
#define KNN_SMEM (OFF_S + 128 * S_STRIDE * 4)

__device__ __forceinline__ void stage_tile(const float* __restrict__ x, int gbase,
                                           char* smem, int hi_off, int lo_off, int tid)
{
    const float2* xg = (const float2*)(x) + (size_t)gbase * 32;
    #pragma unroll
    for (int it = 0; it < 16; ++it) {
        int t = it * 256 + tid;          // 4096 b32 slots
        int r = t >> 5, c4 = t & 31;
        float2 v = xg[r * 32 + c4];
        __nv_bfloat16 h0 = __float2bfloat16(v.x);
        __nv_bfloat16 h1 = __float2bfloat16(v.y);
        __nv_bfloat16 l0 = __float2bfloat16(v.x - __bfloat162float(h0));
        __nv_bfloat16 l1 = __float2bfloat16(v.y - __bfloat162float(h1));
        uint32_t hp = (uint32_t)__bfloat16_as_ushort(h0) | ((uint32_t)__bfloat16_as_ushort(h1) << 16);
        uint32_t lp = (uint32_t)__bfloat16_as_ushort(l0) | ((uint32_t)__bfloat16_as_ushort(l1) << 16);
        int q  = (c4 >> 2) ^ (r & 7);                    // permuted 16B chunk
        int by = r * 128 + q * 16 + (c4 & 3) * 4;
        *(uint32_t*)(smem + hi_off + by) = hp;
        *(uint32_t*)(smem + lo_off + by) = lp;
    }
}

__device__ __forceinline__ uint32_t tile_addr(uint32_t base, int r, int c) {
    return base + r * 128 + ((c ^ (r & 7)) << 4);
}

__global__ void __launch_bounds__(256, 2) knn_tc_kernel(const float* __restrict__ x)
{
    extern __shared__ char smem[];
    uint32_t sb = smem_u32(smem);
    float* sqs = (float*)(smem + OFF_SQ);
    float* S   = (float*)(smem + OFF_S);

    int tid  = threadIdx.x;
    int w    = tid >> 5, lane = tid & 31;
    int b    = blockIdx.y;
    int gi0  = b * NPER + blockIdx.x * 128;

    stage_tile(x, gi0, smem, OFF_XI_H, OFF_XI_L, tid);
    __syncthreads();

    // persistent A fragments: warp w = i-rows [16w, 16w+16)
    uint32_t ah[4][4], al[4][4];
    {
        int r = w * 16 + (lane & 15);
        int qh = (lane >> 4);
        #pragma unroll
        for (int ks = 0; ks < 4; ++ks) {
            ldmatrix_x4(ah[ks][0], ah[ks][1], ah[ks][2], ah[ks][3],
                        tile_addr(sb + OFF_XI_H, r, 2 * ks + qh));
            ldmatrix_x4(al[ks][0], al[ks][1], al[ks][2], al[ks][3],
                        tile_addr(sb + OFF_XI_L, r, 2 * ks + qh));
        }
    }

    // scan assignment: row = tid & 127, col window = (tid >> 7) * 32
    int srow  = tid & 127;
    int scol  = (tid >> 7) * 32;

    float topD[HCAND];
    int   topI[HCAND];
    #pragma unroll
    for (int k = 0; k < HCAND; ++k) { topD[k] = FLT_MAX; topI[k] = 0; }
    float worst = FLT_MAX;

    for (int t = 0; t < NPER / 128; ++t) {
        int jt = t * 128;
        stage_tile(x, b * NPER + jt, smem, OFF_XJ_H, OFF_XJ_L, tid);
        if (tid < 128) sqs[tid] = d_sq[b * NPER + jt + tid];
        __syncthreads();

        #pragma unroll
        for (int h = 0; h < 2; ++h) {
            // ---- MMA: warp computes its 16 rows x 64 cols ----
            float acc[8][4];
            #pragma unroll
            for (int nt = 0; nt < 8; ++nt)
                #pragma unroll
                for (int c = 0; c < 4; ++c) acc[nt][c] = 0.f;

            int e  = lane & 15;
            int nr = h * 64 + (e & 7);
            int qb = (e >> 3);
            #pragma unroll
            for (int nt = 0; nt < 8; ++nt) {
                #pragma unroll
                for (int ks = 0; ks < 4; ++ks) {
                    uint32_t bh0, bh1, bl0, bl1;
                    ldmatrix_x2(bh0, bh1, tile_addr(sb + OFF_XJ_H, nr + nt * 8, 2 * ks + qb));
                    ldmatrix_x2(bl0, bl1, tile_addr(sb + OFF_XJ_L, nr + nt * 8, 2 * ks + qb));
                    mma_bf16(acc[nt], ah[ks], bh0, bh1);
                    mma_bf16(acc[nt], al[ks], bh0, bh1);
                    mma_bf16(acc[nt], ah[ks], bl0, bl1);
                }
            }

            int r0 = w * 16 + (lane >> 2);
            int c0 = (lane & 3) * 2;
            #pragma unroll
            for (int nt = 0; nt < 8; ++nt) {
                int c = nt * 8 + c0;
                S[r0 * S_STRIDE + c]           = acc[nt][0];
                S[r0 * S_STRIDE + c + 1]       = acc[nt][1];
                S[(r0 + 8) * S_STRIDE + c]     = acc[nt][2];
                S[(r0 + 8) * S_STRIDE + c + 1] = acc[nt][3];
            }
            __syncthreads();

            // ---- scan: 256 threads, each scans 32 cols of its row ----
            {
                const float* Srow = &S[srow * S_STRIDE + scol];
                const float* sqh  = &sqs[h * 64 + scol];
                int jbase = jt + h * 64 + scol;
                #pragma unroll 4
                for (int c = 0; c < 32; ++c) {
                    float key = fmaf(-2.f, Srow[c], sqh[c]);
                    if (key < worst) {
                        float dd = key;
                        int   ii = jbase + c;
                        #pragma unroll
                        for (int p = 0; p < HCAND; ++p) {
                            float od = topD[p]; int oi = topI[p];
                            bool cc = dd < od;
                            topD[p] = cc ? dd : od;  topI[p] = cc ? ii : oi;
                            dd = cc ? od : dd;       ii = cc ? oi : ii;
                        }
                        worst = topD[HCAND - 1];
                    }
                }
            }
            __syncthreads();
        }
    }

    // write candidate sets: thread t<128 -> slots 0..15, t>=128 -> slots 16..31
    {
        int gi = gi0 + srow;
        int s0 = (tid >> 7) * HCAND;
        #pragma unroll
        for (int k = 0; k < HCAND; ++k)
            d_cand[(size_t)gi * CAND + s0 + k] = b * NPER + topI[k];
    }
}

// ---------------------------------------------------------------------------
// Kernel 3 (fused): exact fp32 rescore of 32 candidates -> top-16 -> edge-MLP
// max epilogue. Warp per point. Candidates from disjoint j-halves => unique.
// ---------------------------------------------------------------------------
__global__ __launch_bounds__(256) void rescore_gather_kernel(
    const float* __restrict__ x, float* __restrict__ out,
    const float* __restrict__ bias)
{
    int warp = threadIdx.x >> 5, lane = threadIdx.x & 31;
    int n = blockIdx.x * 8 + warp;

    float xi0 = x[(size_t)n * DIM + lane];
    float xi1 = x[(size_t)n * DIM + 32 + lane];

    int myJ = d_cand[(size_t)n * CAND + lane];

    // exact keys: 32 warp-cooperative dots
    float myKey = FLT_MAX;
    #pragma unroll
    for (int c = 0; c < CAND; ++c) {
        int j = __shfl_sync(0xffffffffu, myJ, c);
        float p = xi0 * x[(size_t)j * DIM + lane] + xi1 * x[(size_t)j * DIM + 32 + lane];
        #pragma unroll
        for (int off = 16; off; off >>= 1) p += __shfl_xor_sync(0xffffffffu, p, off);
        if (lane == c) myKey = fmaf(-2.f, p, d_sq[j]);
    }

    // total-order rank (stable tie-break by smaller index)
    int rank = 0;
    #pragma unroll
    for (int m = 0; m < CAND; ++m) {
        float km = __shfl_sync(0xffffffffu, myKey, m);
        int   jm = __shfl_sync(0xffffffffu, myJ,   m);
        rank += (km < myKey) || (km == myKey && jm < myJ);
    }

    // gather: max over the 16 best candidates' C rows
    float m0 = -FLT_MAX, m1 = -FLT_MAX;
    #pragma unroll
    for (int k = 0; k < KNN; ++k) {
        uint32_t bal = __ballot_sync(0xffffffffu, rank == k);
        int src = __ffs(bal) - 1;
        int j = __shfl_sync(0xffffffffu, myJ, src);
        m0 = fmaxf(m0, d_C[(size_t)j * DIM + lane]);
        m1 = fmaxf(m1, d_C[(size_t)j * DIM + 32 + lane]);
    }
    float a0 = d_P1[(size_t)n * DIM + lane]      - d_C[(size_t)n * DIM + lane]      + bias[lane];
    float a1 = d_P1[(size_t)n * DIM + 32 + lane] - d_C[(size_t)n * DIM + 32 + lane] + bias[32 + lane];
    out[(size_t)n * DIM + lane]      = fmaxf(a0 + m0, 0.f);
    out[(size_t)n * DIM + 32 + lane] = fmaxf(a1 + m1, 0.f);
}

// ---------------------------------------------------------------------------
extern "C" void kernel_launch(void* const* d_in, const int* in_sizes, int n_in,
                              void* d_out, int out_size)
{
    const float* x      = (const float*)d_in[0];
    // d_in[1] = batch (structure known: repeat(arange(64), 2048)) — unused
    const float* weight = (const float*)d_in[2];
    const float* bias   = (const float*)d_in[3];
    float* out = (float*)d_out;

    cudaFuncSetAttribute(knn_tc_kernel, cudaFuncAttributeMaxDynamicSharedMemorySize, KNN_SMEM);

    precompute_kernel<<<dim3(NTOT / 64, 2), 256>>>(x, weight);
    knn_tc_kernel<<<dim3(NPER / 128, BATCH), 256, KNN_SMEM>>>(x);
    rescore_gather_kernel<<<NTOT / 8, 256>>>(x, out, bias);
}

// round 16
// speedup vs baseline: 1.1544x; 1.0176x over previous
#include <cuda_runtime.h>
#include <cuda_bf16.h>
#include <cstdint>
#include <float.h>

#define BATCH 64
#define NPER  2048
#define DIM   64
#define KNN   16
#define CAND  20
#define NTOT  (BATCH * NPER)

// scratch (no cudaMalloc allowed)
__device__ float d_sq[NTOT];
__device__ float d_P1[NTOT * DIM];     // X @ W1^T
__device__ float d_C[NTOT * DIM];      // X @ W2^T
__device__ int   d_cand[NTOT * CAND];  // approx top-20 candidates (global idx)

// ===========================================================================
// warp-MMA helpers (base sm_103 target: mma.sync + ldmatrix, NO tcgen05)
// ===========================================================================
__device__ __forceinline__ uint32_t smem_u32(const void* p) {
    uint32_t a;
    asm("{ .reg .u64 t; cvta.to.shared.u64 t, %1; cvt.u32.u64 %0, t; }" : "=r"(a) : "l"(p));
    return a;
}
__device__ __forceinline__ void ldmatrix_x4(uint32_t& r0, uint32_t& r1, uint32_t& r2, uint32_t& r3, uint32_t addr) {
    asm volatile("ldmatrix.sync.aligned.m8n8.x4.shared.b16 {%0,%1,%2,%3},[%4];"
                 : "=r"(r0), "=r"(r1), "=r"(r2), "=r"(r3) : "r"(addr));
}
__device__ __forceinline__ void ldmatrix_x2(uint32_t& r0, uint32_t& r1, uint32_t addr) {
    asm volatile("ldmatrix.sync.aligned.m8n8.x2.shared.b16 {%0,%1},[%2];"
                 : "=r"(r0), "=r"(r1) : "r"(addr));
}
__device__ __forceinline__ void mma_bf16(float* d, const uint32_t* a, uint32_t b0, uint32_t b1) {
    asm volatile("mma.sync.aligned.m16n8k16.row.col.f32.bf16.bf16.f32 "
                 "{%0,%1,%2,%3}, {%4,%5,%6,%7}, {%8,%9}, {%0,%1,%2,%3};"
                 : "+f"(d[0]), "+f"(d[1]), "+f"(d[2]), "+f"(d[3])
                 : "r"(a[0]), "r"(a[1]), "r"(a[2]), "r"(a[3]), "r"(b0), "r"(b1));
}

// ---------------------------------------------------------------------------
// Kernel 1: GEMM half: X[131072 x 64] @ Wh^T[64 x 64], h = blockIdx.y (W1/W2).
// ---------------------------------------------------------------------------
#define XT_STRIDE 68
__global__ __launch_bounds__(256) void precompute_kernel(
    const float* __restrict__ x, const float* __restrict__ weight)
{
    __shared__ float s_v[DIM * 64];          // [d][o]      16 KB
    __shared__ float s_xt[64 * XT_STRIDE];   // [p][d] pad  17 KB

    int tid   = threadIdx.x;
    int nbase = blockIdx.x * 64;
    int h     = blockIdx.y;

    for (int t = tid; t < DIM * 64; t += 256) {
        int o = t >> 6, d = t & 63;
        s_v[d * 64 + o] = weight[o * 128 + h * 64 + d];
    }
    for (int t = tid; t < 64 * 64; t += 256) {
        int p = t >> 6, d = t & 63;
        s_xt[p * XT_STRIDE + d] = x[(size_t)(nbase + p) * DIM + d];
    }
    __syncthreads();

    if (h == 0) {
        int p = tid >> 2, q = tid & 3;
        float ss = 0.f;
        #pragma unroll
        for (int s = 0; s < 16; ++s) {
            float v = s_xt[p * XT_STRIDE + q * 16 + s];
            ss = fmaf(v, v, ss);
        }
        ss += __shfl_xor_sync(0xffffffffu, ss, 1);
        ss += __shfl_xor_sync(0xffffffffu, ss, 2);
        if (q == 0) d_sq[nbase + p] = ss;
    }

    int og = tid & 15, pg = tid >> 4;
    int j_base = og * 4, p_base = pg * 4;

    float acc[4][4];
    #pragma unroll
    for (int pi = 0; pi < 4; ++pi)
        #pragma unroll
        for (int jj = 0; jj < 4; ++jj) acc[pi][jj] = 0.f;

    #pragma unroll
    for (int d4 = 0; d4 < 16; ++d4) {
        float4 xv[4];
        #pragma unroll
        for (int pi = 0; pi < 4; ++pi)
            xv[pi] = *(const float4*)&s_xt[(p_base + pi) * XT_STRIDE + d4 * 4];
        #pragma unroll
        for (int dd = 0; dd < 4; ++dd) {
            float4 wv = *(const float4*)&s_v[(d4 * 4 + dd) * 64 + j_base];
            float xs[4] = { ((const float*)&xv[0])[dd], ((const float*)&xv[1])[dd],
                            ((const float*)&xv[2])[dd], ((const float*)&xv[3])[dd] };
            #pragma unroll
            for (int pi = 0; pi < 4; ++pi) {
                acc[pi][0] = fmaf(xs[pi], wv.x, acc[pi][0]);
                acc[pi][1] = fmaf(xs[pi], wv.y, acc[pi][1]);
                acc[pi][2] = fmaf(xs[pi], wv.z, acc[pi][2]);
                acc[pi][3] = fmaf(xs[pi], wv.w, acc[pi][3]);
            }
        }
    }

    float* dst = h ? d_C : d_P1;
    #pragma unroll
    for (int pi = 0; pi < 4; ++pi) {
        *(float4*)&dst[(size_t)(nbase + p_base + pi) * DIM + j_base] =
            make_float4(acc[pi][0], acc[pi][1], acc[pi][2], acc[pi][3]);
    }
}

// ---------------------------------------------------------------------------
// Kernel 2: warp-specialized tensor-core kNN.
// Warps 0-3 (producers): MMA S quarter-tiles (128 x 32) into double-buffered
// smem; also stage Xj/sq. Warps 4-7 (scanners): thread-per-row register
// top-20 over the previous quarter. No persistent A-frags -> no spills.
// ---------------------------------------------------------------------------
#define OFF_SQ0  0
#define OFF_SQ1  512
#define OFF_XI_H 1024
#define OFF_XI_L (OFF_XI_H + 16384)
#define OFF_XJ_H (OFF_XI_L + 16384)
#define OFF_XJ_L (OFF_XJ_H + 16384)
#define OFF_S0   (OFF_XJ_L + 16384)
#define S_STRIDE 33
#define S_BYTES  (128 * S_STRIDE * 4)
#define OFF_S1   (OFF_S0 + S_BYTES)
#define KNN_SMEM (OFF_S1 + S_BYTES)

// stage 128 fp32 points -> hi/lo bf16 tiles ([point][64] 128B rows,
// 16B chunks xor-permuted by (row & 7)), with NT participating threads.
template <int NT>
__device__ __forceinline__ void stage_tile(const float* __restrict__ x, int gbase,
                                           char* smem, int hi_off, int lo_off, int tid)
{
    const float2* xg = (const float2*)(x) + (size_t)gbase * 32;
    #pragma unroll
    for (int it = 0; it < 4096 / NT; ++it) {
        int t = it * NT + tid;
        int r = t >> 5, c4 = t & 31;
        float2 v = xg[r * 32 + c4];
        __nv_bfloat16 h0 = __float2bfloat16(v.x);
        __nv_bfloat16 h1 = __float2bfloat16(v.y);
        __nv_bfloat16 l0 = __float2bfloat16(v.x - __bfloat162float(h0));
        __nv_bfloat16 l1 = __float2bfloat16(v.y - __bfloat162float(h1));
        uint32_t hp = (uint32_t)__bfloat16_as_ushort(h0) | ((uint32_t)__bfloat16_as_ushort(h1) << 16);
        uint32_t lp = (uint32_t)__bfloat16_as_ushort(l0) | ((uint32_t)__bfloat16_as_ushort(l1) << 16);
        int q  = (c4 >> 2) ^ (r & 7);
        int by = r * 128 + q * 16 + (c4 & 3) * 4;
        *(uint32_t*)(smem + hi_off + by) = hp;
        *(uint32_t*)(smem + lo_off + by) = lp;
    }
}

__device__ __forceinline__ uint32_t tile_addr(uint32_t base, int r, int c) {
    return base + r * 128 + ((c ^ (r & 7)) << 4);
}

// producer: compute S[128 rows][32 cols] for quarter q of current Xj tile.
// warp mw handles i-rows [32mw, 32mw+32). 3 products: hh + lh + hl.
__device__ __forceinline__ void produce_quarter(uint32_t sb, float* S,
                                                int mw, int lane, int q)
{
    float acc[2][4][4];
    #pragma unroll
    for (int m = 0; m < 2; ++m)
        #pragma unroll
        for (int nt = 0; nt < 4; ++nt)
            #pragma unroll
            for (int c = 0; c < 4; ++c) acc[m][nt][c] = 0.f;

    int e  = lane & 15;
    int ar = mw * 32 + e;
    int aq = lane >> 4;

    #pragma unroll
    for (int ks = 0; ks < 4; ++ks) {
        uint32_t ah0[4], ah1[4], al0[4], al1[4];
        ldmatrix_x4(ah0[0], ah0[1], ah0[2], ah0[3], tile_addr(sb + OFF_XI_H, ar,      2 * ks + aq));
        ldmatrix_x4(ah1[0], ah1[1], ah1[2], ah1[3], tile_addr(sb + OFF_XI_H, ar + 16, 2 * ks + aq));
        ldmatrix_x4(al0[0], al0[1], al0[2], al0[3], tile_addr(sb + OFF_XI_L, ar,      2 * ks + aq));
        ldmatrix_x4(al1[0], al1[1], al1[2], al1[3], tile_addr(sb + OFF_XI_L, ar + 16, 2 * ks + aq));
        #pragma unroll
        for (int nt = 0; nt < 4; ++nt) {
            int brow = q * 32 + nt * 8 + (e & 7);
            int bq   = e >> 3;
            uint32_t bh0, bh1, bl0, bl1;
            ldmatrix_x2(bh0, bh1, tile_addr(sb + OFF_XJ_H, brow, 2 * ks + bq));
            ldmatrix_x2(bl0, bl1, tile_addr(sb + OFF_XJ_L, brow, 2 * ks + bq));
            mma_bf16(acc[0][nt], ah0, bh0, bh1);
            mma_bf16(acc[0][nt], al0, bh0, bh1);
            mma_bf16(acc[0][nt], ah0, bl0, bl1);
            mma_bf16(acc[1][nt], ah1, bh0, bh1);
            mma_bf16(acc[1][nt], al1, bh0, bh1);
            mma_bf16(acc[1][nt], ah1, bl0, bl1);
        }
    }

    int r0 = mw * 32 + (lane >> 2);
    int c0 = (lane & 3) * 2;
    #pragma unroll
    for (int m = 0; m < 2; ++m) {
        #pragma unroll
        for (int nt = 0; nt < 4; ++nt) {
            int r = r0 + m * 16;
            int c = nt * 8 + c0;
            S[r * S_STRIDE + c]           = acc[m][nt][0];
            S[r * S_STRIDE + c + 1]       = acc[m][nt][1];
            S[(r + 8) * S_STRIDE + c]     = acc[m][nt][2];
            S[(r + 8) * S_STRIDE + c + 1] = acc[m][nt][3];
        }
    }
}

__global__ void __launch_bounds__(256, 2) knn_tc_kernel(const float* __restrict__ x)
{
    extern __shared__ char smem[];
    uint32_t sb = smem_u32(smem);

    int tid  = threadIdx.x;
    int w    = tid >> 5, lane = tid & 31;
    int b    = blockIdx.y;
    int gi0  = b * NPER + blockIdx.x * 128;

    stage_tile<256>(x, gi0, smem, OFF_XI_H, OFF_XI_L, tid);
    __syncthreads();

    bool producer = (w < 4);
    int  sr = (w - 4) * 32 + lane;   // scanner's i-row

    float topD[CAND];
    int   topI[CAND];
    #pragma unroll
    for (int k = 0; k < CAND; ++k) { topD[k] = FLT_MAX; topI[k] = 0; }
    float worst = FLT_MAX;

    const int NSTEP = (NPER / 128) * 4;   // 64 quarter-steps
    for (int s = 0; s <= NSTEP; ++s) {
        if (producer && s < NSTEP) {
            int t = s >> 2, q = s & 3;
            if (q == 0) {
                stage_tile<128>(x, b * NPER + t * 128, smem, OFF_XJ_H, OFF_XJ_L, tid);
                ((float*)(smem + ((t & 1) ? OFF_SQ1 : OFF_SQ0)))[tid] = d_sq[b * NPER + t * 128 + tid];
                asm volatile("bar.sync 1, 128;" ::: "memory");
            }
            float* Sb = (float*)(smem + ((s & 1) ? OFF_S1 : OFF_S0));
            produce_quarter(sb, Sb, w, lane, q);
        }
        if (!producer && s > 0) {
            int ps = s - 1;
            int pt = ps >> 2, pq = ps & 3;
            const float* Srow = (const float*)(smem + ((ps & 1) ? OFF_S1 : OFF_S0)) + sr * S_STRIDE;
            const float* sq   = (const float*)(smem + ((pt & 1) ? OFF_SQ1 : OFF_SQ0)) + pq * 32;
            int jbase = pt * 128 + pq * 32;
            #pragma unroll 4
            for (int c = 0; c < 32; ++c) {
                float key = fmaf(-2.f, Srow[c], sq[c]);
                if (key < worst) {
                    float dd = key;
                    int   ii = jbase + c;
                    #pragma unroll
                    for (int p = 0; p < CAND; ++p) {
                        float od = topD[p]; int oi = topI[p];
                        bool cc = dd < od;
                        topD[p] = cc ? dd : od;  topI[p] = cc ? ii : oi;
                        dd = cc ? od : dd;       ii = cc ? oi : ii;
                    }
                    worst = topD[CAND - 1];
                }
            }
        }
        __syncthreads();
    }

    if (!producer) {
        int gi = gi0 + sr;
        #pragma unroll
        for (int k = 0; k < CAND; ++k)
            d_cand[(size_t)gi * CAND + k] = b * NPER + topI[k];
    }
}

// ---------------------------------------------------------------------------
// Kernel 3 (fused): exact fp32 rescore of 20 candidates -> top-16 -> edge-MLP
// max epilogue. Warp per point. Stable tie-break by smaller index.
// ---------------------------------------------------------------------------
__global__ __launch_bounds__(256) void rescore_gather_kernel(
    const float* __restrict__ x, float* __restrict__ out,
    const float* __restrict__ bias)
{
    int warp = threadIdx.x >> 5, lane = threadIdx.x & 31;
    int n = blockIdx.x * 8 + warp;

    float xi0 = x[(size_t)n * DIM + lane];
    float xi1 = x[(size_t)n * DIM + 32 + lane];

    int   myJ   = (lane < CAND) ? d_cand[(size_t)n * CAND + lane] : 0;
    float myKey = FLT_MAX;

    #pragma unroll
    for (int c = 0; c < CAND; ++c) {
        int j = __shfl_sync(0xffffffffu, myJ, c);
        float p = xi0 * x[(size_t)j * DIM + lane] + xi1 * x[(size_t)j * DIM + 32 + lane];
        #pragma unroll
        for (int off = 16; off; off >>= 1) p += __shfl_xor_sync(0xffffffffu, p, off);
        if (lane == c) myKey = fmaf(-2.f, p, d_sq[j]);
    }

    int rank = 0;
    #pragma unroll
    for (int m = 0; m < CAND; ++m) {
        float km = __shfl_sync(0xffffffffu, myKey, m);
        int   jm = __shfl_sync(0xffffffffu, myJ,   m);
        rank += (km < myKey) || (km == myKey && jm < myJ);
    }
    if (lane >= CAND) rank = CAND;   // exclude invalid lanes from top-16

    float m0 = -FLT_MAX, m1 = -FLT_MAX;
    #pragma unroll
    for (int k = 0; k < KNN; ++k) {
        uint32_t bal = __ballot_sync(0xffffffffu, rank == k);
        int src = __ffs(bal) - 1;
        int j = __shfl_sync(0xffffffffu, myJ, src);
        m0 = fmaxf(m0, d_C[(size_t)j * DIM + lane]);
        m1 = fmaxf(m1, d_C[(size_t)j * DIM + 32 + lane]);
    }
    float a0 = d_P1[(size_t)n * DIM + lane]      - d_C[(size_t)n * DIM + lane]      + bias[lane];
    float a1 = d_P1[(size_t)n * DIM + 32 + lane] - d_C[(size_t)n * DIM + 32 + lane] + bias[32 + lane];
    out[(size_t)n * DIM + lane]      = fmaxf(a0 + m0, 0.f);
    out[(size_t)n * DIM + 32 + lane] = fmaxf(a1 + m1, 0.f);
}

// ---------------------------------------------------------------------------
extern "C" void kernel_launch(void* const* d_in, const int* in_sizes, int n_in,
                              void* d_out, int out_size)
{
    const float* x      = (const float*)d_in[0];
    // d_in[1] = batch (structure known: repeat(arange(64), 2048)) — unused
    const float* weight = (const float*)d_in[2];
    const float* bias   = (const float*)d_in[3];
    float* out = (float*)d_out;

    cudaFuncSetAttribute(knn_tc_kernel, cudaFuncAttributeMaxDynamicSharedMemorySize, KNN_SMEM);

    precompute_kernel<<<dim3(NTOT / 64, 2), 256>>>(x, weight);
    knn_tc_kernel<<<dim3(NPER / 128, BATCH), 256, KNN_SMEM>>>(x);
    rescore_gather_kernel<<<NTOT / 8, 256>>>(x, out, bias);
}

// round 17
// speedup vs baseline: 1.7795x; 1.5415x over previous
#include <cuda_runtime.h>
#include <cuda_bf16.h>
#include <cstdint>
#include <float.h>

#define BATCH 64
#define NPER  2048
#define DIM   64
#define KNN   16
#define CAND  20
#define NTOT  (BATCH * NPER)

// scratch (no cudaMalloc allowed)
__device__ float d_sq[NTOT];
__device__ float d_P1[NTOT * DIM];     // X @ W1^T
__device__ float d_C[NTOT * DIM];      // X @ W2^T
__device__ int   d_cand[NTOT * CAND];  // approx top-20 candidates (global idx)

// ===========================================================================
// warp-MMA helpers (base sm_103 target: mma.sync + ldmatrix, NO tcgen05)
// ===========================================================================
__device__ __forceinline__ uint32_t smem_u32(const void* p) {
    uint32_t a;
    asm("{ .reg .u64 t; cvta.to.shared.u64 t, %1; cvt.u32.u64 %0, t; }" : "=r"(a) : "l"(p));
    return a;
}
__device__ __forceinline__ void ldmatrix_x4(uint32_t& r0, uint32_t& r1, uint32_t& r2, uint32_t& r3, uint32_t addr) {
    asm volatile("ldmatrix.sync.aligned.m8n8.x4.shared.b16 {%0,%1,%2,%3},[%4];"
                 : "=r"(r0), "=r"(r1), "=r"(r2), "=r"(r3) : "r"(addr));
}
__device__ __forceinline__ void ldmatrix_x2(uint32_t& r0, uint32_t& r1, uint32_t addr) {
    asm volatile("ldmatrix.sync.aligned.m8n8.x2.shared.b16 {%0,%1},[%2];"
                 : "=r"(r0), "=r"(r1) : "r"(addr));
}
__device__ __forceinline__ void mma_bf16(float* d, const uint32_t* a, uint32_t b0, uint32_t b1) {
    asm volatile("mma.sync.aligned.m16n8k16.row.col.f32.bf16.bf16.f32 "
                 "{%0,%1,%2,%3}, {%4,%5,%6,%7}, {%8,%9}, {%0,%1,%2,%3};"
                 : "+f"(d[0]), "+f"(d[1]), "+f"(d[2]), "+f"(d[3])
                 : "r"(a[0]), "r"(a[1]), "r"(a[2]), "r"(a[3]), "r"(b0), "r"(b1));
}

// ---------------------------------------------------------------------------
// Kernel 1: precompute GEMM  X[131072 x 64] @ V[64 x 128] (V = [W1^T | W2^T]).
// 128 points x 128 outputs per CTA, 256 threads, 8x8 accumulators.
// Both operands staged TRANSPOSED ([d][p], [d][o], stride 132) so the inner
// loop does float4 LDS on both sides (16 FFMA per LDS.128). Staging stores
// use p/o as the lane-fast index -> conflict-free STS. Also emits sq norms.
// ---------------------------------------------------------------------------
#define PRE_STRIDE 132
#define PRE_SMEM   (2 * DIM * PRE_STRIDE * 4)   // s_x + s_v, 66 KB

__global__ void __launch_bounds__(256, 2) precompute_kernel(
    const float* __restrict__ x, const float* __restrict__ weight)
{
    extern __shared__ float psm[];
    float* s_x = psm;                       // [d][p] stride 132
    float* s_v = psm + DIM * PRE_STRIDE;    // [d][o] stride 132

    int tid   = threadIdx.x;
    int nbase = blockIdx.x * 128;

    // stage x transposed: idx -> (p = idx&127 lane-fast, c4 = idx>>7)
    #pragma unroll
    for (int it = 0; it < 8; ++it) {
        int idx = it * 256 + tid;
        int p = idx & 127, c4 = idx >> 7;
        float4 v = *(const float4*)&x[(size_t)(nbase + p) * DIM + c4 * 4];
        s_x[(c4 * 4 + 0) * PRE_STRIDE + p] = v.x;
        s_x[(c4 * 4 + 1) * PRE_STRIDE + p] = v.y;
        s_x[(c4 * 4 + 2) * PRE_STRIDE + p] = v.z;
        s_x[(c4 * 4 + 3) * PRE_STRIDE + p] = v.w;
    }
    // stage V transposed: o = idx&127 lane-fast, dc = idx>>7
    #pragma unroll
    for (int it = 0; it < 8; ++it) {
        int idx = it * 256 + tid;
        int o = idx & 127, dc = idx >> 7;
        float4 v = *(const float4*)&weight[(o & 63) * 128 + ((o >> 6) << 6) + dc * 4];
        s_v[(dc * 4 + 0) * PRE_STRIDE + o] = v.x;
        s_v[(dc * 4 + 1) * PRE_STRIDE + o] = v.y;
        s_v[(dc * 4 + 2) * PRE_STRIDE + o] = v.z;
        s_v[(dc * 4 + 3) * PRE_STRIDE + o] = v.w;
    }
    __syncthreads();

    // squared norms (threads 0..127; p lane-fast -> conflict-free)
    if (tid < 128) {
        float ss = 0.f;
        #pragma unroll
        for (int d = 0; d < DIM; ++d) {
            float v = s_x[d * PRE_STRIDE + tid];
            ss = fmaf(v, v, ss);
        }
        d_sq[nbase + tid] = ss;
    }

    // register-blocked GEMM: thread (og = tid&15, pg = tid>>4) -> 8 outs x 8 pts
    int og = tid & 15, pg = tid >> 4;
    float acc[8][8];
    #pragma unroll
    for (int pi = 0; pi < 8; ++pi)
        #pragma unroll
        for (int k = 0; k < 8; ++k) acc[pi][k] = 0.f;

    #pragma unroll 4
    for (int d = 0; d < DIM; ++d) {
        float4 xv0 = *(const float4*)&s_x[d * PRE_STRIDE + pg * 8];
        float4 xv1 = *(const float4*)&s_x[d * PRE_STRIDE + pg * 8 + 4];
        float4 wv0 = *(const float4*)&s_v[d * PRE_STRIDE + og * 8];
        float4 wv1 = *(const float4*)&s_v[d * PRE_STRIDE + og * 8 + 4];
        float xs[8] = { xv0.x, xv0.y, xv0.z, xv0.w, xv1.x, xv1.y, xv1.z, xv1.w };
        float ws[8] = { wv0.x, wv0.y, wv0.z, wv0.w, wv1.x, wv1.y, wv1.z, wv1.w };
        #pragma unroll
        for (int pi = 0; pi < 8; ++pi)
            #pragma unroll
            for (int k = 0; k < 8; ++k)
                acc[pi][k] = fmaf(xs[pi], ws[k], acc[pi][k]);
    }

    float* dst = (og < 8) ? d_P1 : d_C;
    int ob = (og & 7) * 8;
    #pragma unroll
    for (int pi = 0; pi < 8; ++pi) {
        float* dp = &dst[(size_t)(nbase + pg * 8 + pi) * DIM + ob];
        *(float4*)(dp)     = make_float4(acc[pi][0], acc[pi][1], acc[pi][2], acc[pi][3]);
        *(float4*)(dp + 4) = make_float4(acc[pi][4], acc[pi][5], acc[pi][6], acc[pi][7]);
    }
}

// ---------------------------------------------------------------------------
// Kernel 2: approximate kNN via warp mma.sync (bf16 hi/lo, 3 products).
// VERBATIM the 1425us-measured structure: CTA = 128 i-points x 256 threads,
// A-frags reloaded per half, register top-20 per scanning thread (tid<128).
// ---------------------------------------------------------------------------
#define OFF_SQ   0
#define OFF_XI_H 1024
#define OFF_XI_L (OFF_XI_H + 16384)
#define OFF_XJ_H (OFF_XI_L + 16384)
#define OFF_XJ_L (OFF_XJ_H + 16384)
#define OFF_S    (OFF_XJ_L + 16384)
#define S_STRIDE 65
#define KNN_SMEM (OFF_S + 128 * S_STRIDE * 4)

__device__ __forceinline__ void stage_tile(const float* __restrict__ x, int gbase,
                                           char* smem, int hi_off, int lo_off, int tid)
{
    const float2* xg = (const float2*)(x) + (size_t)gbase * 32;
    #pragma unroll
    for (int it = 0; it < 16; ++it) {
        int t = it * 256 + tid;          // 4096 b32 slots
        int r = t >> 5, c4 = t & 31;
        float2 v = xg[r * 32 + c4];
        __nv_bfloat16 h0 = __float2bfloat16(v.x);
        __nv_bfloat16 h1 = __float2bfloat16(v.y);
        __nv_bfloat16 l0 = __float2bfloat16(v.x - __bfloat162float(h0));
        __nv_bfloat16 l1 = __float2bfloat16(v.y - __bfloat162float(h1));
        uint32_t hp = (uint32_t)__bfloat16_as_ushort(h0) | ((uint32_t)__bfloat16_as_ushort(h1) << 16);
        uint32_t lp = (uint32_t)__bfloat16_as_ushort(l0) | ((uint32_t)__bfloat16_as_ushort(l1) << 16);
        int q  = (c4 >> 2) ^ (r & 7);                    // permuted 16B chunk
        int by = r * 128 + q * 16 + (c4 & 3) * 4;
        *(uint32_t*)(smem + hi_off + by) = hp;
        *(uint32_t*)(smem + lo_off + by) = lp;
    }
}

__device__ __forceinline__ uint32_t tile_addr(uint32_t base, int r, int c) {
    return base + r * 128 + ((c ^ (r & 7)) << 4);
}

__global__ void __launch_bounds__(256, 2) knn_tc_kernel(const float* __restrict__ x)
{
    extern __shared__ char smem[];
    uint32_t sb = smem_u32(smem);
    float* sqs = (float*)(smem + OFF_SQ);
    float* S   = (float*)(smem + OFF_S);

    int tid  = threadIdx.x;
    int w    = tid >> 5, lane = tid & 31;
    int b    = blockIdx.y;
    int gi0  = b * NPER + blockIdx.x * 128;

    stage_tile(x, gi0, smem, OFF_XI_H, OFF_XI_L, tid);
    __syncthreads();

    float topD[CAND];
    int   topI[CAND];
    #pragma unroll
    for (int k = 0; k < CAND; ++k) { topD[k] = FLT_MAX; topI[k] = 0; }
    float worst = FLT_MAX;

    for (int t = 0; t < NPER / 128; ++t) {
        int jt = t * 128;
        stage_tile(x, b * NPER + jt, smem, OFF_XJ_H, OFF_XJ_L, tid);
        if (tid < 128) sqs[tid] = d_sq[b * NPER + jt + tid];
        __syncthreads();

        #pragma unroll
        for (int h = 0; h < 2; ++h) {
            // reload A fragments each half (frees regs during scan phase)
            uint32_t ah[4][4], al[4][4];
            {
                int r = w * 16 + (lane & 15);
                int qh = (lane >> 4);
                #pragma unroll
                for (int ks = 0; ks < 4; ++ks) {
                    ldmatrix_x4(ah[ks][0], ah[ks][1], ah[ks][2], ah[ks][3],
                                tile_addr(sb + OFF_XI_H, r, 2 * ks + qh));
                    ldmatrix_x4(al[ks][0], al[ks][1], al[ks][2], al[ks][3],
                                tile_addr(sb + OFF_XI_L, r, 2 * ks + qh));
                }
            }

            float acc[8][4];
            #pragma unroll
            for (int nt = 0; nt < 8; ++nt)
                #pragma unroll
                for (int c = 0; c < 4; ++c) acc[nt][c] = 0.f;

            int e  = lane & 15;
            int nr = h * 64 + (e & 7);
            int qb = (e >> 3);
            #pragma unroll
            for (int nt = 0; nt < 8; ++nt) {
                #pragma unroll
                for (int ks = 0; ks < 4; ++ks) {
                    uint32_t bh0, bh1, bl0, bl1;
                    ldmatrix_x2(bh0, bh1, tile_addr(sb + OFF_XJ_H, nr + nt * 8, 2 * ks + qb));
                    ldmatrix_x2(bl0, bl1, tile_addr(sb + OFF_XJ_L, nr + nt * 8, 2 * ks + qb));
                    mma_bf16(acc[nt], ah[ks], bh0, bh1);
                    mma_bf16(acc[nt], al[ks], bh0, bh1);
                    mma_bf16(acc[nt], ah[ks], bl0, bl1);
                }
            }

            int r0 = w * 16 + (lane >> 2);
            int c0 = (lane & 3) * 2;
            #pragma unroll
            for (int nt = 0; nt < 8; ++nt) {
                int c = nt * 8 + c0;
                S[r0 * S_STRIDE + c]           = acc[nt][0];
                S[r0 * S_STRIDE + c + 1]       = acc[nt][1];
                S[(r0 + 8) * S_STRIDE + c]     = acc[nt][2];
                S[(r0 + 8) * S_STRIDE + c + 1] = acc[nt][3];
            }
            __syncthreads();

            if (tid < 128) {
                const float* Srow = &S[tid * S_STRIDE];
                int jbase = jt + h * 64;
                #pragma unroll 4
                for (int c = 0; c < 64; ++c) {
                    float key = fmaf(-2.f, Srow[c], sqs[h * 64 + c]);
                    if (key < worst) {
                        float dd = key;
                        int   ii = jbase + c;
                        #pragma unroll
                        for (int p = 0; p < CAND; ++p) {
                            float od = topD[p]; int oi = topI[p];
                            bool cc = dd < od;
                            topD[p] = cc ? dd : od;  topI[p] = cc ? ii : oi;
                            dd = cc ? od : dd;       ii = cc ? oi : ii;
                        }
                        worst = topD[CAND - 1];
                    }
                }
            }
            __syncthreads();
        }
    }

    if (tid < 128) {
        int gi = gi0 + tid;
        #pragma unroll
        for (int k = 0; k < CAND; ++k)
            d_cand[(size_t)gi * CAND + k] = b * NPER + topI[k];
    }
}

// ---------------------------------------------------------------------------
// Kernel 3 (fused): exact fp32 rescore of 20 candidates -> top-16 -> edge-MLP
// max epilogue. Warp per point. Stable tie-break by smaller index.
// ---------------------------------------------------------------------------
__global__ __launch_bounds__(256) void rescore_gather_kernel(
    const float* __restrict__ x, float* __restrict__ out,
    const float* __restrict__ bias)
{
    int warp = threadIdx.x >> 5, lane = threadIdx.x & 31;
    int n = blockIdx.x * 8 + warp;

    float xi0 = x[(size_t)n * DIM + lane];
    float xi1 = x[(size_t)n * DIM + 32 + lane];

    int   myJ   = (lane < CAND) ? d_cand[(size_t)n * CAND + lane] : 0;
    float myKey = FLT_MAX;

    #pragma unroll
    for (int c = 0; c < CAND; ++c) {
        int j = __shfl_sync(0xffffffffu, myJ, c);
        float p = xi0 * x[(size_t)j * DIM + lane] + xi1 * x[(size_t)j * DIM + 32 + lane];
        #pragma unroll
        for (int off = 16; off; off >>= 1) p += __shfl_xor_sync(0xffffffffu, p, off);
        if (lane == c) myKey = fmaf(-2.f, p, d_sq[j]);
    }

    int rank = 0;
    #pragma unroll
    for (int m = 0; m < CAND; ++m) {
        float km = __shfl_sync(0xffffffffu, myKey, m);
        int   jm = __shfl_sync(0xffffffffu, myJ,   m);
        rank += (km < myKey) || (km == myKey && jm < myJ);
    }
    if (lane >= CAND) rank = CAND;   // exclude invalid lanes from top-16

    float m0 = -FLT_MAX, m1 = -FLT_MAX;
    #pragma unroll
    for (int k = 0; k < KNN; ++k) {
        uint32_t bal = __ballot_sync(0xffffffffu, rank == k);
        int src = __ffs(bal) - 1;
        int j = __shfl_sync(0xffffffffu, myJ, src);
        m0 = fmaxf(m0, d_C[(size_t)j * DIM + lane]);
        m1 = fmaxf(m1, d_C[(size_t)j * DIM + 32 + lane]);
    }
    float a0 = d_P1[(size_t)n * DIM + lane]      - d_C[(size_t)n * DIM + lane]      + bias[lane];
    float a1 = d_P1[(size_t)n * DIM + 32 + lane] - d_C[(size_t)n * DIM + 32 + lane] + bias[32 + lane];
    out[(size_t)n * DIM + lane]      = fmaxf(a0 + m0, 0.f);
    out[(size_t)n * DIM + 32 + lane] = fmaxf(a1 + m1, 0.f);
}

// ---------------------------------------------------------------------------
extern "C" void kernel_launch(void* const* d_in, const int* in_sizes, int n_in,
                              void* d_out, int out_size)
{
    const float* x      = (const float*)d_in[0];
    // d_in[1] = batch (structure known: repeat(arange(64), 2048)) — unused
    const float* weight = (const float*)d_in[2];
    const float* bias   = (const float*)d_in[3];
    float* out = (float*)d_out;

    cudaFuncSetAttribute(knn_tc_kernel, cudaFuncAttributeMaxDynamicSharedMemorySize, KNN_SMEM);
    cudaFuncSetAttribute(precompute_kernel, cudaFuncAttributeMaxDynamicSharedMemorySize, PRE_SMEM);

    precompute_kernel<<<NTOT / 128, 256, PRE_SMEM>>>(x, weight);
    knn_tc_kernel<<<dim3(NPER / 128, BATCH), 256, KNN_SMEM>>>(x);
    rescore_gather_kernel<<<NTOT / 8, 256>>>(x, out, bias);
}